// round 13
// baseline (speedup 1.0000x reference)
#include <cuda_runtime.h>
#include <cuda_fp16.h>
#include <math.h>
#include <stdint.h>

#define BB 2
#define VV 6
#define CC 256
#define QQ 900
#define KP 4
#define H0 64
#define W0 176
#define H1 32
#define W1 88
#define NH 8
#define HD 32
#define ATT_SCALE 0.17677669529663689f
#define HW0 (H0*W0)
#define HW1 (H1*W1)
#define PT0 (HW0/64)
#define PT1 (HW1/64)
#define NIT ((QQ + 63) / 64)     // 15 KV tiles
#define NSPLIT 4
#define ZZ (BB*NH)               // 16

// ---------------- scratch (device globals; no runtime allocation) ----------------
__device__ __half g_featT0[(size_t)BB*VV*HW0*CC];   // [B,V,H,W,C] fp16
__device__ __half g_featT1[(size_t)BB*VV*HW1*CC];
__device__ float  g_sampled[BB*QQ*CC];
__device__ __half g_qp[BB*QQ*CC];
__device__ __half g_kp[BB*QQ*CC];
__device__ __half g_vp[BB*QQ*CC];
__device__ float  g_attno[BB*QQ*CC];
__device__ float  g_po[(size_t)NSPLIT*ZZ*QQ*HD];    // unnormalized partial O
__device__ float  g_pm[NSPLIT*ZZ*QQ];               // partial row max
__device__ float  g_pl[NSPLIT*ZZ*QQ];               // partial row sum

__device__ __forceinline__ uint32_t f22h(float x, float y) {
    __half2 h = __floats2half2_rn(x, y);
    return *reinterpret_cast<uint32_t*>(&h);
}

// ---------------- feature transpose v3: both levels, one launch ----------------
__global__ void transpose_kernel(const float* __restrict__ f0, const float* __restrict__ f1) {
    __shared__ float tile[64][65];
    int bid = blockIdx.x;
    const int NT0 = PT0 * 4 * BB * VV;
    const float* src; __half* dst; int HW, pt, ct;
    if (bid < NT0) {
        int r = bid; int bv = r / (PT0 * 4); r %= PT0 * 4; pt = r >> 2; ct = r & 3;
        HW = HW0; src = f0 + (size_t)bv * CC * HW0; dst = g_featT0 + (size_t)bv * HW0 * CC;
    } else {
        int r = bid - NT0; int bv = r / (PT1 * 4); r %= PT1 * 4; pt = r >> 2; ct = r & 3;
        HW = HW1; src = f1 + (size_t)bv * CC * HW1; dst = g_featT1 + (size_t)bv * HW1 * CC;
    }
    int c0 = ct * 64, p0 = pt * 64;
    int tid = threadIdx.x;

    int rc = tid >> 4;
    int rp = (tid & 15) * 4;
    #pragma unroll
    for (int i = 0; i < 4; i++) {
        int c = rc + i * 16;
        float4 v = *(const float4*)(src + (size_t)(c0 + c) * HW + p0 + rp);
        tile[c][rp + 0] = v.x; tile[c][rp + 1] = v.y;
        tile[c][rp + 2] = v.z; tile[c][rp + 3] = v.w;
    }
    __syncthreads();

    int wp = tid >> 3;
    int wg = (tid & 7) * 8;
    #pragma unroll
    for (int i = 0; i < 2; i++) {
        int p = wp + i * 32;
        uint4 o;
        o.x = f22h(tile[wg + 0][p], tile[wg + 1][p]);
        o.y = f22h(tile[wg + 2][p], tile[wg + 3][p]);
        o.z = f22h(tile[wg + 4][p], tile[wg + 5][p]);
        o.w = f22h(tile[wg + 6][p], tile[wg + 7][p]);
        *(uint4*)(dst + (size_t)(p0 + p) * CC + c0 + wg) = o;
    }
}

// ---------------- sampling (unchanged) ----------------
__global__ void sample_kernel(const float* __restrict__ refs,
                              const float* __restrict__ intr,
                              const float* __restrict__ extr) {
    __shared__ float         s_w[4][48][4];
    __shared__ const __half* s_p[4][48][4];
    __shared__ int           s_valid[4][48];
    __shared__ float         s_cnt[4];
    int tid = threadIdx.y * 64 + threadIdx.x;
    int bq0 = blockIdx.x * 4;

    if (tid < 192) {
        int qy = tid / 48, t = tid % 48;
        int bq = bq0 + qy;
        int b = bq / QQ, q = bq % QQ;
        int level = t / 24, r = t % 24, v = r >> 2, k = r & 3;
        int bv = b * VV + v;
        const float kpx[4] = {0.f, 2.f, 0.f, -2.f};
        const float kpy[4] = {0.f, 0.f, 2.f, 0.f};
        const float* rp = refs + (b * QQ + q) * 3;
        float rx = rp[0] + kpx[k], ry = rp[1] + kpy[k], rz = rp[2];
        const float* E = extr + bv * 16;
        float c0 = E[0]*rx + E[1]*ry + E[2]*rz + E[3];
        float c1 = E[4]*rx + E[5]*ry + E[6]*rz + E[7];
        float c2 = E[8]*rx + E[9]*ry + E[10]*rz + E[11];
        const float* I = intr + bv * 9;
        float u  = I[0]*c0 + I[1]*c1 + I[2]*c2;
        float w_ = I[3]*c0 + I[4]*c1 + I[5]*c2;
        float z  = I[6]*c0 + I[7]*c1 + I[8]*c2;
        float zs = (fabsf(z) > 1e-6f) ? z : 1e-6f;
        float uz = u / zs, vz = w_ / zs;
        s_valid[qy][t] = (z > 0.f);
        int H = level ? H1 : H0, W = level ? W1 : W0;
        const __half* base = level ? g_featT1 : g_featT0;
        float gx = 2.f * uz / (float)(W - 1) - 1.f;
        float gy = 2.f * vz / (float)(H - 1) - 1.f;
        float x = (gx + 1.f) * 0.5f * (float)(W - 1);
        float y = (gy + 1.f) * 0.5f * (float)(H - 1);
        float x0f = floorf(x), y0f = floorf(y);
        float wx1 = x - x0f, wx0 = 1.f - wx1;
        float wy1 = y - y0f, wy0 = 1.f - wy1;
        #pragma unroll
        for (int c4 = 0; c4 < 4; c4++) {
            int dx = c4 & 1, dy = c4 >> 1;
            float xf = x0f + (float)dx, yf = y0f + (float)dy;
            bool inb = (xf >= 0.f) && (xf <= (float)(W - 1)) && (yf >= 0.f) && (yf <= (float)(H - 1));
            int xi = min(max((int)xf, 0), W - 1);
            int yi = min(max((int)yf, 0), H - 1);
            s_w[qy][t][c4] = inb ? (dx ? wx1 : wx0) * (dy ? wy1 : wy0) : 0.f;
            s_p[qy][t][c4] = base + (((size_t)bv * H + yi) * W + xi) * CC;
        }
    }
    __syncthreads();
    if (tid < 4) {
        float c = 0.f;
        for (int t = 0; t < 24; t++) c += s_valid[tid][t] ? 1.f : 0.f;
        s_cnt[tid] = 0.5f / fmaxf(c, 1.f);
    }
    __syncthreads();

    int qy = threadIdx.y, c = threadIdx.x * 4;
    float4 acc = make_float4(0.f, 0.f, 0.f, 0.f);
    #pragma unroll 4
    for (int t = 0; t < 48; t++) {
        if (!s_valid[qy][t]) continue;
        #pragma unroll
        for (int j = 0; j < 4; j++) {
            float w = s_w[qy][t][j];
            uint2 raw = *(const uint2*)(s_p[qy][t][j] + c);
            __half2 h0 = *reinterpret_cast<__half2*>(&raw.x);
            __half2 h1 = *reinterpret_cast<__half2*>(&raw.y);
            float2 f0 = __half22float2(h0);
            float2 f1 = __half22float2(h1);
            acc.x = fmaf(w, f0.x, acc.x);
            acc.y = fmaf(w, f0.y, acc.y);
            acc.z = fmaf(w, f1.x, acc.z);
            acc.w = fmaf(w, f1.y, acc.w);
        }
    }
    float sc = s_cnt[qy];
    int bq = bq0 + qy;
    *(float4*)(g_sampled + (size_t)bq * CC + c) =
        make_float4(acc.x * sc, acc.y * sc, acc.z * sc, acc.w * sc);
}

// ---------------- mma helper ----------------
__device__ __forceinline__ void mma16(float* c, const uint32_t* a, const uint32_t* b) {
    asm volatile(
        "mma.sync.aligned.m16n8k16.row.col.f32.f16.f16.f32 "
        "{%0,%1,%2,%3},{%4,%5,%6,%7},{%8,%9},{%0,%1,%2,%3};\n"
        : "+f"(c[0]), "+f"(c[1]), "+f"(c[2]), "+f"(c[3])
        : "r"(a[0]), "r"(a[1]), "r"(a[2]), "r"(a[3]), "r"(b[0]), "r"(b[1]));
}

// ---------------- pipelined fp16 projection GEMM (64x64 tile) ----------------
#define GEMM_SMEM ((2*64*18 + 2*16*72) * 4)
template<typename OutT>
__device__ __forceinline__ void gemm_body(
    const float* __restrict__ A, const float* __restrict__ B,
    OutT* __restrict__ C, const float* __restrict__ bias,
    int M, int N, int K, int lda, int ldb, int ldc, float alpha)
{
    extern __shared__ uint32_t gsm[];
    uint32_t (*As)[64][18] = (uint32_t(*)[64][18])gsm;
    uint32_t (*Bs)[16][72] = (uint32_t(*)[16][72])(gsm + 2*64*18);
    int tid = threadIdx.x;
    int warp = tid >> 5, lane = tid & 31;
    int g = lane >> 2, tg = lane & 3;
    int wm0 = (warp >> 1) * 16, wn0 = (warp & 1) * 32;
    int m0 = blockIdx.y * 64, n0 = blockIdx.x * 64;
    float acc[4][4] = {};

    int arow = tid >> 3, ac4 = (tid & 7) * 4, ac2 = (tid & 7) * 2;

    float4 aR[2], bR[2];
    auto loadA = [&](int k0) {
        #pragma unroll
        for (int i = 0; i < 2; i++) {
            int row = arow + i * 32;
            int gm = m0 + row, gk = k0 + ac4;
            aR[i] = (gm < M) ? *(const float4*)(A + (size_t)gm * lda + gk)
                             : make_float4(0.f, 0.f, 0.f, 0.f);
        }
    };
    auto loadB = [&](int k0) {
        #pragma unroll
        for (int i = 0; i < 2; i++) {
            int n = arow + i * 32;
            int gn = n0 + n, gk = k0 + ac4;
            bR[i] = (gn < N) ? *(const float4*)(B + (size_t)gn * ldb + gk)
                             : make_float4(0.f, 0.f, 0.f, 0.f);
        }
    };
    auto stage = [&](int buf) {
        #pragma unroll
        for (int i = 0; i < 2; i++) {
            int row = arow + i * 32;
            As[buf][row][ac2+0] = f22h(aR[i].x, aR[i].y);
            As[buf][row][ac2+1] = f22h(aR[i].z, aR[i].w);
        }
        #pragma unroll
        for (int i = 0; i < 2; i++) {
            int n = arow + i * 32;
            Bs[buf][ac2+0][n] = f22h(bR[i].x, bR[i].y);
            Bs[buf][ac2+1][n] = f22h(bR[i].z, bR[i].w);
        }
    };

    loadA(0); loadB(0);
    int nk = K >> 5;
    int buf = 0;
    for (int kt = 0; kt < nk; kt++) {
        stage(buf);
        __syncthreads();
        if (kt + 1 < nk) { loadA((kt + 1) * 32); loadB((kt + 1) * 32); }
        #pragma unroll
        for (int ko = 0; ko < 2; ko++) {
            int koff = ko * 8;
            uint32_t a[4], bfr[4][2];
            a[0] = As[buf][wm0 + g][koff + tg];
            a[1] = As[buf][wm0 + g + 8][koff + tg];
            a[2] = As[buf][wm0 + g][koff + tg + 4];
            a[3] = As[buf][wm0 + g + 8][koff + tg + 4];
            #pragma unroll
            for (int ni = 0; ni < 4; ni++) {
                int cn = wn0 + ni * 8 + g;
                bfr[ni][0] = Bs[buf][koff + tg][cn];
                bfr[ni][1] = Bs[buf][koff + tg + 4][cn];
            }
            #pragma unroll
            for (int ni = 0; ni < 4; ni++)
                mma16(acc[ni], a, bfr[ni]);
        }
        buf ^= 1;
    }

    #pragma unroll
    for (int ni = 0; ni < 4; ni++) {
        int r0 = m0 + wm0 + g;
        int cc0 = n0 + wn0 + ni * 8 + tg * 2;
        #pragma unroll
        for (int e = 0; e < 4; e++) {
            int r = r0 + (e >> 1) * 8;
            int cn = cc0 + (e & 1);
            if (r < M && cn < N) {
                float val = acc[ni][e];
                if (bias) val += bias[cn];
                val *= alpha;
                C[(size_t)r * ldc + cn] = (OutT)val;
            }
        }
    }
}

__global__ void gemm_proj(const float* __restrict__ A, const float* __restrict__ B,
                          float* __restrict__ C, const float* __restrict__ bias) {
    gemm_body<float>(A, B, C, bias, BB * QQ, CC, CC, CC, CC, CC, 1.f);
}

__global__ void gemm_qkv(const float* __restrict__ qry, const float* __restrict__ sampled,
                         const float* __restrict__ Wq, const float* __restrict__ Wk,
                         const float* __restrict__ Wv,
                         const float* __restrict__ bq, const float* __restrict__ bk,
                         const float* __restrict__ bv,
                         __half* __restrict__ qp, __half* __restrict__ kp, __half* __restrict__ vp) {
    int z = blockIdx.z;
    const float* A = (z == 0) ? qry : sampled;
    const float* B = (z == 0) ? Wq : ((z == 1) ? Wk : Wv);
    const float* bi = (z == 0) ? bq : ((z == 1) ? bk : bv);
    __half* C = (z == 0) ? qp : ((z == 1) ? kp : vp);
    float alpha = (z == 0) ? ATT_SCALE : 1.f;
    gemm_body<__half>(A, B, C, bi, BB * QQ, CC, CC, CC, CC, CC, alpha);
}

// ---------------- split-K flash attention: grid (qtiles, ZZ, NSPLIT), 128 threads ----------------
#define FLASH_SMEM ((64*18 + 2*16*68 + 2*32*36 + 64*34) * 4)

__global__ void flash_kernel(const __half* __restrict__ qp, const __half* __restrict__ kp,
                             const __half* __restrict__ vp) {
    extern __shared__ uint32_t fsm[];
    uint32_t (*Qs)[18]     = (uint32_t(*)[18])fsm;
    uint32_t (*Ks)[16][68] = (uint32_t(*)[16][68])(fsm + 64*18);
    uint32_t (*Vs)[32][36] = (uint32_t(*)[32][36])(fsm + 64*18 + 2*16*68);
    uint32_t (*Ps)[34]     = (uint32_t(*)[34])(fsm + 64*18 + 2*16*68 + 2*32*36);

    int z = blockIdx.y;
    int b = z / NH, h = z % NH;
    int q0 = blockIdx.x * 64;
    int sp = blockIdx.z;
    const int TPS = (NIT + NSPLIT - 1) / NSPLIT;   // 4 tiles per split
    int it0 = sp * TPS;
    int it1 = min(NIT, it0 + TPS);
    int tid = threadIdx.x;
    int warp = tid >> 5, lane = tid & 31;
    int g = lane >> 2, tg = lane & 3;
    int wr0 = warp * 16;

    const __half* qbase = qp + (size_t)b * QQ * CC + h * HD;
    const __half* kbase = kp + (size_t)b * QQ * CC + h * HD;
    const __half* vbase = vp + (size_t)b * QQ * CC + h * HD;

    #pragma unroll
    for (int i = 0; i < 4; i++) {
        int lin = tid + i * 128;
        int row = lin >> 3, ch2 = (lin & 7) * 2, c4 = (lin & 7) * 4;
        uint2 raw = make_uint2(0u, 0u);
        if (q0 + row < QQ) raw = *(const uint2*)(qbase + (size_t)(q0 + row) * CC + c4);
        Qs[row][ch2]     = raw.x;
        Qs[row][ch2 + 1] = raw.y;
    }

    int krow = tid >> 2;
    int kc8 = (tid & 3) * 8;
    int kw4 = (tid & 3) * 4;
    uint4 kr[2], va, vb;
    auto loadKV = [&](int k0) {
        #pragma unroll
        for (int j = 0; j < 2; j++) {
            int gk = k0 + krow + j * 32;
            kr[j] = (gk < QQ) ? *(const uint4*)(kbase + (size_t)gk * CC + kc8)
                              : make_uint4(0u, 0u, 0u, 0u);
        }
        int gva = k0 + 2 * krow, gvb = gva + 1;
        va = (gva < QQ) ? *(const uint4*)(vbase + (size_t)gva * CC + kc8) : make_uint4(0u, 0u, 0u, 0u);
        vb = (gvb < QQ) ? *(const uint4*)(vbase + (size_t)gvb * CC + kc8) : make_uint4(0u, 0u, 0u, 0u);
    };
    auto stageKV = [&](int buf) {
        #pragma unroll
        for (int j = 0; j < 2; j++) {
            int key = krow + j * 32;
            Ks[buf][kw4 + 0][key] = kr[j].x;
            Ks[buf][kw4 + 1][key] = kr[j].y;
            Ks[buf][kw4 + 2][key] = kr[j].z;
            Ks[buf][kw4 + 3][key] = kr[j].w;
        }
        Vs[buf][krow][kc8 + 0] = __byte_perm(va.x, vb.x, 0x5410);
        Vs[buf][krow][kc8 + 1] = __byte_perm(va.x, vb.x, 0x7632);
        Vs[buf][krow][kc8 + 2] = __byte_perm(va.y, vb.y, 0x5410);
        Vs[buf][krow][kc8 + 3] = __byte_perm(va.y, vb.y, 0x7632);
        Vs[buf][krow][kc8 + 4] = __byte_perm(va.z, vb.z, 0x5410);
        Vs[buf][krow][kc8 + 5] = __byte_perm(va.z, vb.z, 0x7632);
        Vs[buf][krow][kc8 + 6] = __byte_perm(va.w, vb.w, 0x5410);
        Vs[buf][krow][kc8 + 7] = __byte_perm(va.w, vb.w, 0x7632);
    };

    float m0r = -1e30f, m1r = -1e30f;
    float l0 = 0.f, l1 = 0.f;
    float oacc[4][4] = {};

    loadKV(it0 * 64);
    int buf = 0;
    for (int it = it0; it < it1; it++) {
        stageKV(buf);
        __syncthreads();
        if (it + 1 < it1) loadKV((it + 1) * 64);

        float sacc[8][4] = {};
        #pragma unroll
        for (int ko = 0; ko < 2; ko++) {
            int koff = ko * 8;
            uint32_t a[4];
            a[0] = Qs[wr0 + g][koff + tg];
            a[1] = Qs[wr0 + g + 8][koff + tg];
            a[2] = Qs[wr0 + g][koff + tg + 4];
            a[3] = Qs[wr0 + g + 8][koff + tg + 4];
            #pragma unroll
            for (int ni = 0; ni < 8; ni++) {
                uint32_t bf[2];
                int cn = ni * 8 + g;
                bf[0] = Ks[buf][koff + tg][cn];
                bf[1] = Ks[buf][koff + tg + 4][cn];
                mma16(sacc[ni], a, bf);
            }
        }

        int cbase = it * 64;
        float r0 = -1e30f, r1 = -1e30f;
        #pragma unroll
        for (int ni = 0; ni < 8; ni++) {
            #pragma unroll
            for (int e = 0; e < 4; e++) {
                int gk = cbase + ni * 8 + tg * 2 + (e & 1);
                float s = sacc[ni][e];
                if (gk >= QQ) s = -1e30f;
                sacc[ni][e] = s;
                if (e < 2) r0 = fmaxf(r0, s); else r1 = fmaxf(r1, s);
            }
        }
        r0 = fmaxf(r0, __shfl_xor_sync(0xffffffffu, r0, 1));
        r0 = fmaxf(r0, __shfl_xor_sync(0xffffffffu, r0, 2));
        r1 = fmaxf(r1, __shfl_xor_sync(0xffffffffu, r1, 1));
        r1 = fmaxf(r1, __shfl_xor_sync(0xffffffffu, r1, 2));

        float nm0 = fmaxf(m0r, r0), nm1 = fmaxf(m1r, r1);
        float sc0 = __expf(m0r - nm0), sc1 = __expf(m1r - nm1);
        m0r = nm0; m1r = nm1;

        float s0 = 0.f, s1 = 0.f;
        #pragma unroll
        for (int ni = 0; ni < 8; ni++) {
            float p0 = __expf(sacc[ni][0] - m0r);
            float p1 = __expf(sacc[ni][1] - m0r);
            float p2 = __expf(sacc[ni][2] - m1r);
            float p3 = __expf(sacc[ni][3] - m1r);
            Ps[wr0 + g][ni * 4 + tg]     = f22h(p0, p1);
            Ps[wr0 + g + 8][ni * 4 + tg] = f22h(p2, p3);
            s0 += p0 + p1;
            s1 += p2 + p3;
        }
        s0 += __shfl_xor_sync(0xffffffffu, s0, 1);
        s0 += __shfl_xor_sync(0xffffffffu, s0, 2);
        s1 += __shfl_xor_sync(0xffffffffu, s1, 1);
        s1 += __shfl_xor_sync(0xffffffffu, s1, 2);
        l0 = l0 * sc0 + s0;
        l1 = l1 * sc1 + s1;

        #pragma unroll
        for (int ni = 0; ni < 4; ni++) {
            oacc[ni][0] *= sc0; oacc[ni][1] *= sc0;
            oacc[ni][2] *= sc1; oacc[ni][3] *= sc1;
        }
        __syncwarp();

        #pragma unroll
        for (int kk2 = 0; kk2 < 32; kk2 += 8) {
            uint32_t a[4];
            a[0] = Ps[wr0 + g][kk2 + tg];
            a[1] = Ps[wr0 + g + 8][kk2 + tg];
            a[2] = Ps[wr0 + g][kk2 + tg + 4];
            a[3] = Ps[wr0 + g + 8][kk2 + tg + 4];
            #pragma unroll
            for (int ni = 0; ni < 4; ni++) {
                uint32_t bf[2];
                int cn = ni * 8 + g;
                bf[0] = Vs[buf][kk2 + tg][cn];
                bf[1] = Vs[buf][kk2 + tg + 4][cn];
                mma16(oacc[ni], a, bf);
            }
        }
        buf ^= 1;
    }

    // write partials: unnormalized O, m, l
    float* po = g_po + (((size_t)sp * ZZ + z) * QQ) * HD;
    float* pm = g_pm + (sp * ZZ + z) * QQ;
    float* pl = g_pl + (sp * ZZ + z) * QQ;
    #pragma unroll
    for (int ni = 0; ni < 4; ni++) {
        #pragma unroll
        for (int e = 0; e < 4; e++) {
            int row = wr0 + g + ((e >> 1) << 3);
            int col = ni * 8 + tg * 2 + (e & 1);
            int q = q0 + row;
            if (q < QQ) po[(size_t)q * HD + col] = oacc[ni][e];
        }
    }
    if (tg == 0) {
        int qa = q0 + wr0 + g, qb = qa + 8;
        if (qa < QQ) { pm[qa] = m0r; pl[qa] = l0; }
        if (qb < QQ) { pm[qb] = m1r; pl[qb] = l1; }
    }
}

// ---------------- split-K combine ----------------
__global__ void combine_kernel(float* __restrict__ attno) {
    int idx = blockIdx.x * 256 + threadIdx.x;
    if (idx >= ZZ * QQ * HD) return;
    int c = idx & (HD - 1);
    int q = (idx >> 5) % QQ;
    int z = idx / (HD * QQ);
    int b = z / NH, h = z % NH;

    float m = -1e30f;
    #pragma unroll
    for (int s = 0; s < NSPLIT; s++)
        m = fmaxf(m, g_pm[(s * ZZ + z) * QQ + q]);
    float o = 0.f, l = 0.f;
    #pragma unroll
    for (int s = 0; s < NSPLIT; s++) {
        float w = __expf(g_pm[(s * ZZ + z) * QQ + q] - m);
        l += g_pl[(s * ZZ + z) * QQ + q] * w;
        o += g_po[(((size_t)s * ZZ + z) * QQ + q) * HD + c] * w;
    }
    attno[((size_t)b * QQ + q) * CC + h * HD + c] = o / l;
}

// ---------------- host launcher ----------------
extern "C" void kernel_launch(void* const* d_in, const int* in_sizes, int n_in,
                              void* d_out, int out_size) {
    const float* f0   = (const float*)d_in[0];
    const float* f1   = (const float*)d_in[1];
    const float* refs = (const float*)d_in[2];
    const float* intr = (const float*)d_in[3];
    const float* extr = (const float*)d_in[4];
    const float* qry  = (const float*)d_in[5];
    const float* Wq   = (const float*)d_in[6];
    const float* bq   = (const float*)d_in[7];
    const float* Wk   = (const float*)d_in[8];
    const float* bk   = (const float*)d_in[9];
    const float* Wv   = (const float*)d_in[10];
    const float* bv   = (const float*)d_in[11];
    const float* Wo   = (const float*)d_in[12];
    const float* bo   = (const float*)d_in[13];
    float* out = (float*)d_out;

    __half *qp, *kp, *vp;
    float *sampled, *attno;
    cudaGetSymbolAddress((void**)&sampled, g_sampled);
    cudaGetSymbolAddress((void**)&qp, g_qp);
    cudaGetSymbolAddress((void**)&kp, g_kp);
    cudaGetSymbolAddress((void**)&vp, g_vp);
    cudaGetSymbolAddress((void**)&attno, g_attno);

    cudaFuncSetAttribute(gemm_qkv, cudaFuncAttributeMaxDynamicSharedMemorySize, GEMM_SMEM);
    cudaFuncSetAttribute(gemm_proj, cudaFuncAttributeMaxDynamicSharedMemorySize, GEMM_SMEM);
    cudaFuncSetAttribute(flash_kernel, cudaFuncAttributeMaxDynamicSharedMemorySize, FLASH_SMEM);

    const int NTILES = (PT0 * 4 + PT1 * 4) * BB * VV;
    transpose_kernel<<<NTILES, 256>>>(f0, f1);
    sample_kernel<<<(BB * QQ) / 4, dim3(64, 4)>>>(refs, intr, extr);

    const int M = BB * QQ;  // 1800
    gemm_qkv<<<dim3(CC / 64, (M + 63) / 64, 3), 256, GEMM_SMEM>>>(
        qry, sampled, Wq, Wk, Wv, bq, bk, bv, qp, kp, vp);

    flash_kernel<<<dim3((QQ + 63) / 64, ZZ, NSPLIT), 128, FLASH_SMEM>>>(qp, kp, vp);
    combine_kernel<<<(ZZ * QQ * HD + 255) / 256, 256>>>(attno);

    gemm_proj<<<dim3(CC / 64, (M + 63) / 64), 256, GEMM_SMEM>>>(attno, Wo, out, bo);
}

// round 15
// speedup vs baseline: 1.0351x; 1.0351x over previous
#include <cuda_runtime.h>
#include <cuda_fp16.h>
#include <math.h>
#include <stdint.h>

#define BB 2
#define VV 6
#define CC 256
#define QQ 900
#define KP 4
#define H0 64
#define W0 176
#define H1 32
#define W1 88
#define NH 8
#define HD 32
#define ATT_SCALE 0.17677669529663689f
#define HW0 (H0*W0)
#define HW1 (H1*W1)
#define PT0 (HW0/64)
#define PT1 (HW1/64)
#define NIT ((QQ + 63) / 64)     // 15 KV tiles
#define NSPLIT 4
#define ZZ (BB*NH)               // 16

// ---------------- scratch (device globals; no runtime allocation) ----------------
__device__ __half g_featT0[(size_t)BB*VV*HW0*CC];   // [B,V,H,W,C] fp16
__device__ __half g_featT1[(size_t)BB*VV*HW1*CC];
__device__ float  g_sampled[BB*QQ*CC];
__device__ __half g_qp[BB*QQ*CC];
__device__ __half g_kp[BB*QQ*CC];
__device__ __half g_vp[BB*QQ*CC];
__device__ float  g_attno[BB*QQ*CC];
__device__ float  g_po[(size_t)NSPLIT*ZZ*QQ*HD];    // unnormalized partial O
__device__ float  g_pm[NSPLIT*ZZ*QQ];               // partial row max
__device__ float  g_pl[NSPLIT*ZZ*QQ];               // partial row sum

__device__ __forceinline__ uint32_t f22h(float x, float y) {
    __half2 h = __floats2half2_rn(x, y);
    return *reinterpret_cast<uint32_t*>(&h);
}

// ---------------- feature transpose v3: both levels, one launch ----------------
__global__ void transpose_kernel(const float* __restrict__ f0, const float* __restrict__ f1) {
    __shared__ float tile[64][65];
    int bid = blockIdx.x;
    const int NT0 = PT0 * 4 * BB * VV;
    const float* src; __half* dst; int HW, pt, ct;
    if (bid < NT0) {
        int r = bid; int bv = r / (PT0 * 4); r %= PT0 * 4; pt = r >> 2; ct = r & 3;
        HW = HW0; src = f0 + (size_t)bv * CC * HW0; dst = g_featT0 + (size_t)bv * HW0 * CC;
    } else {
        int r = bid - NT0; int bv = r / (PT1 * 4); r %= PT1 * 4; pt = r >> 2; ct = r & 3;
        HW = HW1; src = f1 + (size_t)bv * CC * HW1; dst = g_featT1 + (size_t)bv * HW1 * CC;
    }
    int c0 = ct * 64, p0 = pt * 64;
    int tid = threadIdx.x;

    int rc = tid >> 4;
    int rp = (tid & 15) * 4;
    #pragma unroll
    for (int i = 0; i < 4; i++) {
        int c = rc + i * 16;
        float4 v = *(const float4*)(src + (size_t)(c0 + c) * HW + p0 + rp);
        tile[c][rp + 0] = v.x; tile[c][rp + 1] = v.y;
        tile[c][rp + 2] = v.z; tile[c][rp + 3] = v.w;
    }
    __syncthreads();

    int wp = tid >> 3;
    int wg = (tid & 7) * 8;
    #pragma unroll
    for (int i = 0; i < 2; i++) {
        int p = wp + i * 32;
        uint4 o;
        o.x = f22h(tile[wg + 0][p], tile[wg + 1][p]);
        o.y = f22h(tile[wg + 2][p], tile[wg + 3][p]);
        o.z = f22h(tile[wg + 4][p], tile[wg + 5][p]);
        o.w = f22h(tile[wg + 6][p], tile[wg + 7][p]);
        *(uint4*)(dst + (size_t)(p0 + p) * CC + c0 + wg) = o;
    }
}

// ---------------- sampling (unchanged) ----------------
__global__ void sample_kernel(const float* __restrict__ refs,
                              const float* __restrict__ intr,
                              const float* __restrict__ extr) {
    __shared__ float         s_w[4][48][4];
    __shared__ const __half* s_p[4][48][4];
    __shared__ int           s_valid[4][48];
    __shared__ float         s_cnt[4];
    int tid = threadIdx.y * 64 + threadIdx.x;
    int bq0 = blockIdx.x * 4;

    if (tid < 192) {
        int qy = tid / 48, t = tid % 48;
        int bq = bq0 + qy;
        int b = bq / QQ, q = bq % QQ;
        int level = t / 24, r = t % 24, v = r >> 2, k = r & 3;
        int bv = b * VV + v;
        const float kpx[4] = {0.f, 2.f, 0.f, -2.f};
        const float kpy[4] = {0.f, 0.f, 2.f, 0.f};
        const float* rp = refs + (b * QQ + q) * 3;
        float rx = rp[0] + kpx[k], ry = rp[1] + kpy[k], rz = rp[2];
        const float* E = extr + bv * 16;
        float c0 = E[0]*rx + E[1]*ry + E[2]*rz + E[3];
        float c1 = E[4]*rx + E[5]*ry + E[6]*rz + E[7];
        float c2 = E[8]*rx + E[9]*ry + E[10]*rz + E[11];
        const float* I = intr + bv * 9;
        float u  = I[0]*c0 + I[1]*c1 + I[2]*c2;
        float w_ = I[3]*c0 + I[4]*c1 + I[5]*c2;
        float z  = I[6]*c0 + I[7]*c1 + I[8]*c2;
        float zs = (fabsf(z) > 1e-6f) ? z : 1e-6f;
        float uz = u / zs, vz = w_ / zs;
        s_valid[qy][t] = (z > 0.f);
        int H = level ? H1 : H0, W = level ? W1 : W0;
        const __half* base = level ? g_featT1 : g_featT0;
        float gx = 2.f * uz / (float)(W - 1) - 1.f;
        float gy = 2.f * vz / (float)(H - 1) - 1.f;
        float x = (gx + 1.f) * 0.5f * (float)(W - 1);
        float y = (gy + 1.f) * 0.5f * (float)(H - 1);
        float x0f = floorf(x), y0f = floorf(y);
        float wx1 = x - x0f, wx0 = 1.f - wx1;
        float wy1 = y - y0f, wy0 = 1.f - wy1;
        #pragma unroll
        for (int c4 = 0; c4 < 4; c4++) {
            int dx = c4 & 1, dy = c4 >> 1;
            float xf = x0f + (float)dx, yf = y0f + (float)dy;
            bool inb = (xf >= 0.f) && (xf <= (float)(W - 1)) && (yf >= 0.f) && (yf <= (float)(H - 1));
            int xi = min(max((int)xf, 0), W - 1);
            int yi = min(max((int)yf, 0), H - 1);
            s_w[qy][t][c4] = inb ? (dx ? wx1 : wx0) * (dy ? wy1 : wy0) : 0.f;
            s_p[qy][t][c4] = base + (((size_t)bv * H + yi) * W + xi) * CC;
        }
    }
    __syncthreads();
    if (tid < 4) {
        float c = 0.f;
        for (int t = 0; t < 24; t++) c += s_valid[tid][t] ? 1.f : 0.f;
        s_cnt[tid] = 0.5f / fmaxf(c, 1.f);
    }
    __syncthreads();

    int qy = threadIdx.y, c = threadIdx.x * 4;
    float4 acc = make_float4(0.f, 0.f, 0.f, 0.f);
    #pragma unroll 4
    for (int t = 0; t < 48; t++) {
        if (!s_valid[qy][t]) continue;
        #pragma unroll
        for (int j = 0; j < 4; j++) {
            float w = s_w[qy][t][j];
            uint2 raw = *(const uint2*)(s_p[qy][t][j] + c);
            __half2 h0 = *reinterpret_cast<__half2*>(&raw.x);
            __half2 h1 = *reinterpret_cast<__half2*>(&raw.y);
            float2 f0 = __half22float2(h0);
            float2 f1 = __half22float2(h1);
            acc.x = fmaf(w, f0.x, acc.x);
            acc.y = fmaf(w, f0.y, acc.y);
            acc.z = fmaf(w, f1.x, acc.z);
            acc.w = fmaf(w, f1.y, acc.w);
        }
    }
    float sc = s_cnt[qy];
    int bq = bq0 + qy;
    *(float4*)(g_sampled + (size_t)bq * CC + c) =
        make_float4(acc.x * sc, acc.y * sc, acc.z * sc, acc.w * sc);
}

// ---------------- mma helper ----------------
__device__ __forceinline__ void mma16(float* c, const uint32_t* a, const uint32_t* b) {
    asm volatile(
        "mma.sync.aligned.m16n8k16.row.col.f32.f16.f16.f32 "
        "{%0,%1,%2,%3},{%4,%5,%6,%7},{%8,%9},{%0,%1,%2,%3};\n"
        : "+f"(c[0]), "+f"(c[1]), "+f"(c[2]), "+f"(c[3])
        : "r"(a[0]), "r"(a[1]), "r"(a[2]), "r"(a[3]), "r"(b[0]), "r"(b[1]));
}

// ---------------- pipelined fp16 projection GEMM (64x64 tile) ----------------
#define GEMM_SMEM ((2*64*18 + 2*16*72) * 4)
template<typename OutT>
__device__ __forceinline__ void gemm_body(
    const float* __restrict__ A, const float* __restrict__ B,
    OutT* __restrict__ C, const float* __restrict__ bias,
    int M, int N, int K, int lda, int ldb, int ldc, float alpha)
{
    extern __shared__ uint32_t gsm[];
    uint32_t (*As)[64][18] = (uint32_t(*)[64][18])gsm;
    uint32_t (*Bs)[16][72] = (uint32_t(*)[16][72])(gsm + 2*64*18);
    int tid = threadIdx.x;
    int warp = tid >> 5, lane = tid & 31;
    int g = lane >> 2, tg = lane & 3;
    int wm0 = (warp >> 1) * 16, wn0 = (warp & 1) * 32;
    int m0 = blockIdx.y * 64, n0 = blockIdx.x * 64;
    float acc[4][4] = {};

    int arow = tid >> 3, ac4 = (tid & 7) * 4, ac2 = (tid & 7) * 2;

    float4 aR[2], bR[2];
    auto loadA = [&](int k0) {
        #pragma unroll
        for (int i = 0; i < 2; i++) {
            int row = arow + i * 32;
            int gm = m0 + row, gk = k0 + ac4;
            aR[i] = (gm < M) ? *(const float4*)(A + (size_t)gm * lda + gk)
                             : make_float4(0.f, 0.f, 0.f, 0.f);
        }
    };
    auto loadB = [&](int k0) {
        #pragma unroll
        for (int i = 0; i < 2; i++) {
            int n = arow + i * 32;
            int gn = n0 + n, gk = k0 + ac4;
            bR[i] = (gn < N) ? *(const float4*)(B + (size_t)gn * ldb + gk)
                             : make_float4(0.f, 0.f, 0.f, 0.f);
        }
    };
    auto stage = [&](int buf) {
        #pragma unroll
        for (int i = 0; i < 2; i++) {
            int row = arow + i * 32;
            As[buf][row][ac2+0] = f22h(aR[i].x, aR[i].y);
            As[buf][row][ac2+1] = f22h(aR[i].z, aR[i].w);
        }
        #pragma unroll
        for (int i = 0; i < 2; i++) {
            int n = arow + i * 32;
            Bs[buf][ac2+0][n] = f22h(bR[i].x, bR[i].y);
            Bs[buf][ac2+1][n] = f22h(bR[i].z, bR[i].w);
        }
    };

    loadA(0); loadB(0);
    int nk = K >> 5;
    int buf = 0;
    for (int kt = 0; kt < nk; kt++) {
        stage(buf);
        __syncthreads();
        if (kt + 1 < nk) { loadA((kt + 1) * 32); loadB((kt + 1) * 32); }
        #pragma unroll
        for (int ko = 0; ko < 2; ko++) {
            int koff = ko * 8;
            uint32_t a[4], bfr[4][2];
            a[0] = As[buf][wm0 + g][koff + tg];
            a[1] = As[buf][wm0 + g + 8][koff + tg];
            a[2] = As[buf][wm0 + g][koff + tg + 4];
            a[3] = As[buf][wm0 + g + 8][koff + tg + 4];
            #pragma unroll
            for (int ni = 0; ni < 4; ni++) {
                int cn = wn0 + ni * 8 + g;
                bfr[ni][0] = Bs[buf][koff + tg][cn];
                bfr[ni][1] = Bs[buf][koff + tg + 4][cn];
            }
            #pragma unroll
            for (int ni = 0; ni < 4; ni++)
                mma16(acc[ni], a, bfr[ni]);
        }
        buf ^= 1;
    }

    #pragma unroll
    for (int ni = 0; ni < 4; ni++) {
        int r0 = m0 + wm0 + g;
        int cc0 = n0 + wn0 + ni * 8 + tg * 2;
        #pragma unroll
        for (int e = 0; e < 4; e++) {
            int r = r0 + (e >> 1) * 8;
            int cn = cc0 + (e & 1);
            if (r < M && cn < N) {
                float val = acc[ni][e];
                if (bias) val += bias[cn];
                val *= alpha;
                C[(size_t)r * ldc + cn] = (OutT)val;
            }
        }
    }
}

__global__ void gemm_proj(const float* __restrict__ A, const float* __restrict__ B,
                          float* __restrict__ C, const float* __restrict__ bias) {
    gemm_body<float>(A, B, C, bias, BB * QQ, CC, CC, CC, CC, CC, 1.f);
}

__global__ void gemm_qkv(const float* __restrict__ qry, const float* __restrict__ sampled,
                         const float* __restrict__ Wq, const float* __restrict__ Wk,
                         const float* __restrict__ Wv,
                         const float* __restrict__ bq, const float* __restrict__ bk,
                         const float* __restrict__ bv,
                         __half* __restrict__ qp, __half* __restrict__ kp, __half* __restrict__ vp) {
    int z = blockIdx.z;
    const float* A = (z == 0) ? qry : sampled;
    const float* B = (z == 0) ? Wq : ((z == 1) ? Wk : Wv);
    const float* bi = (z == 0) ? bq : ((z == 1) ? bk : bv);
    __half* C = (z == 0) ? qp : ((z == 1) ? kp : vp);
    float alpha = (z == 0) ? ATT_SCALE : 1.f;
    gemm_body<__half>(A, B, C, bi, BB * QQ, CC, CC, CC, CC, CC, alpha);
}

// ---------------- split-K flash attention v6: register Q + register P ----------------
// smem words: Qs[64][18] | Ks[2][16][68] | Vs[2][32][36]
#define FLASH_SMEM ((64*18 + 2*16*68 + 2*32*36) * 4)

__global__ void flash_kernel(const __half* __restrict__ qp, const __half* __restrict__ kp,
                             const __half* __restrict__ vp) {
    extern __shared__ uint32_t fsm[];
    uint32_t (*Qs)[18]     = (uint32_t(*)[18])fsm;
    uint32_t (*Ks)[16][68] = (uint32_t(*)[16][68])(fsm + 64*18);
    uint32_t (*Vs)[32][36] = (uint32_t(*)[32][36])(fsm + 64*18 + 2*16*68);

    int z = blockIdx.y;
    int b = z / NH, h = z % NH;
    int q0 = blockIdx.x * 64;
    int sp = blockIdx.z;
    const int TPS = (NIT + NSPLIT - 1) / NSPLIT;
    int it0 = sp * TPS;
    int it1 = min(NIT, it0 + TPS);
    int tid = threadIdx.x;
    int warp = tid >> 5, lane = tid & 31;
    int g = lane >> 2, tg = lane & 3;
    int wr0 = warp * 16;

    const __half* qbase = qp + (size_t)b * QQ * CC + h * HD;
    const __half* kbase = kp + (size_t)b * QQ * CC + h * HD;
    const __half* vbase = vp + (size_t)b * QQ * CC + h * HD;

    // stage Q to smem
    #pragma unroll
    for (int i = 0; i < 4; i++) {
        int lin = tid + i * 128;
        int row = lin >> 3, ch2 = (lin & 7) * 2, c4 = (lin & 7) * 4;
        uint2 raw = make_uint2(0u, 0u);
        if (q0 + row < QQ) raw = *(const uint2*)(qbase + (size_t)(q0 + row) * CC + c4);
        Qs[row][ch2]     = raw.x;
        Qs[row][ch2 + 1] = raw.y;
    }

    int krow = tid >> 2;
    int kc8 = (tid & 3) * 8;
    int kw4 = (tid & 3) * 4;
    uint4 kr[2], va, vb;
    auto loadKV = [&](int k0) {
        #pragma unroll
        for (int j = 0; j < 2; j++) {
            int gk = k0 + krow + j * 32;
            kr[j] = (gk < QQ) ? *(const uint4*)(kbase + (size_t)gk * CC + kc8)
                              : make_uint4(0u, 0u, 0u, 0u);
        }
        int gva = k0 + 2 * krow, gvb = gva + 1;
        va = (gva < QQ) ? *(const uint4*)(vbase + (size_t)gva * CC + kc8) : make_uint4(0u, 0u, 0u, 0u);
        vb = (gvb < QQ) ? *(const uint4*)(vbase + (size_t)gvb * CC + kc8) : make_uint4(0u, 0u, 0u, 0u);
    };
    auto stageKV = [&](int buf) {
        #pragma unroll
        for (int j = 0; j < 2; j++) {
            int key = krow + j * 32;
            Ks[buf][kw4 + 0][key] = kr[j].x;
            Ks[buf][kw4 + 1][key] = kr[j].y;
            Ks[buf][kw4 + 2][key] = kr[j].z;
            Ks[buf][kw4 + 3][key] = kr[j].w;
        }
        Vs[buf][krow][kc8 + 0] = __byte_perm(va.x, vb.x, 0x5410);
        Vs[buf][krow][kc8 + 1] = __byte_perm(va.x, vb.x, 0x7632);
        Vs[buf][krow][kc8 + 2] = __byte_perm(va.y, vb.y, 0x5410);
        Vs[buf][krow][kc8 + 3] = __byte_perm(va.y, vb.y, 0x7632);
        Vs[buf][krow][kc8 + 4] = __byte_perm(va.z, vb.z, 0x5410);
        Vs[buf][krow][kc8 + 5] = __byte_perm(va.z, vb.z, 0x7632);
        Vs[buf][krow][kc8 + 6] = __byte_perm(va.w, vb.w, 0x5410);
        Vs[buf][krow][kc8 + 7] = __byte_perm(va.w, vb.w, 0x7632);
    };

    // prologue: stage first KV tile, then hoist Q fragments into registers
    loadKV(it0 * 64);
    stageKV(0);
    __syncthreads();
    uint32_t qf[2][4];
    #pragma unroll
    for (int ko = 0; ko < 2; ko++) {
        int koff = ko * 8;
        qf[ko][0] = Qs[wr0 + g][koff + tg];
        qf[ko][1] = Qs[wr0 + g + 8][koff + tg];
        qf[ko][2] = Qs[wr0 + g][koff + tg + 4];
        qf[ko][3] = Qs[wr0 + g + 8][koff + tg + 4];
    }

    float m0r = -1e30f, m1r = -1e30f;
    float l0 = 0.f, l1 = 0.f;
    float oacc[4][4] = {};

    int buf = 0;
    for (int it = it0; it < it1; it++) {
        bool has_next = (it + 1 < it1);
        if (has_next) loadKV((it + 1) * 64);

        // S = Q @ K^T (Q from registers)
        float sacc[8][4] = {};
        #pragma unroll
        for (int ko = 0; ko < 2; ko++) {
            int koff = ko * 8;
            #pragma unroll
            for (int ni = 0; ni < 8; ni++) {
                uint32_t bf[2];
                int cn = ni * 8 + g;
                bf[0] = Ks[buf][koff + tg][cn];
                bf[1] = Ks[buf][koff + tg + 4][cn];
                mma16(sacc[ni], qf[ko], bf);
            }
        }

        // mask + rowmax
        int cbase = it * 64;
        float r0 = -1e30f, r1 = -1e30f;
        #pragma unroll
        for (int ni = 0; ni < 8; ni++) {
            #pragma unroll
            for (int e = 0; e < 4; e++) {
                int gk = cbase + ni * 8 + tg * 2 + (e & 1);
                float s = sacc[ni][e];
                if (gk >= QQ) s = -1e30f;
                sacc[ni][e] = s;
                if (e < 2) r0 = fmaxf(r0, s); else r1 = fmaxf(r1, s);
            }
        }
        r0 = fmaxf(r0, __shfl_xor_sync(0xffffffffu, r0, 1));
        r0 = fmaxf(r0, __shfl_xor_sync(0xffffffffu, r0, 2));
        r1 = fmaxf(r1, __shfl_xor_sync(0xffffffffu, r1, 1));
        r1 = fmaxf(r1, __shfl_xor_sync(0xffffffffu, r1, 2));

        float nm0 = fmaxf(m0r, r0), nm1 = fmaxf(m1r, r1);
        float sc0 = __expf(m0r - nm0), sc1 = __expf(m1r - nm1);
        m0r = nm0; m1r = nm1;

        // P = exp(S - m) -> registers as fp16 A-fragments
        uint32_t pf[8][2];
        float s0 = 0.f, s1 = 0.f;
        #pragma unroll
        for (int ni = 0; ni < 8; ni++) {
            float p0 = __expf(sacc[ni][0] - m0r);
            float p1 = __expf(sacc[ni][1] - m0r);
            float p2 = __expf(sacc[ni][2] - m1r);
            float p3 = __expf(sacc[ni][3] - m1r);
            pf[ni][0] = f22h(p0, p1);
            pf[ni][1] = f22h(p2, p3);
            s0 += p0 + p1;
            s1 += p2 + p3;
        }
        s0 += __shfl_xor_sync(0xffffffffu, s0, 1);
        s0 += __shfl_xor_sync(0xffffffffu, s0, 2);
        s1 += __shfl_xor_sync(0xffffffffu, s1, 1);
        s1 += __shfl_xor_sync(0xffffffffu, s1, 2);
        l0 = l0 * sc0 + s0;
        l1 = l1 * sc1 + s1;

        #pragma unroll
        for (int ni = 0; ni < 4; ni++) {
            oacc[ni][0] *= sc0; oacc[ni][1] *= sc0;
            oacc[ni][2] *= sc1; oacc[ni][3] *= sc1;
        }

        // O += P @ V (P from registers; keys 16 per step)
        #pragma unroll
        for (int t = 0; t < 4; t++) {
            uint32_t a[4];
            a[0] = pf[2 * t][0];
            a[1] = pf[2 * t][1];
            a[2] = pf[2 * t + 1][0];
            a[3] = pf[2 * t + 1][1];
            int kk2 = t * 8;
            #pragma unroll
            for (int ni = 0; ni < 4; ni++) {
                uint32_t bf[2];
                int cn = ni * 8 + g;
                bf[0] = Vs[buf][kk2 + tg][cn];
                bf[1] = Vs[buf][kk2 + tg + 4][cn];
                mma16(oacc[ni], a, bf);
            }
        }

        if (has_next) {
            stageKV(buf ^ 1);
            __syncthreads();
        }
        buf ^= 1;
    }

    // write partials: unnormalized O, m, l
    float* po = g_po + (((size_t)sp * ZZ + z) * QQ) * HD;
    float* pm = g_pm + (sp * ZZ + z) * QQ;
    float* pl = g_pl + (sp * ZZ + z) * QQ;
    #pragma unroll
    for (int ni = 0; ni < 4; ni++) {
        #pragma unroll
        for (int e = 0; e < 4; e++) {
            int row = wr0 + g + ((e >> 1) << 3);
            int col = ni * 8 + tg * 2 + (e & 1);
            int q = q0 + row;
            if (q < QQ) po[(size_t)q * HD + col] = oacc[ni][e];
        }
    }
    if (tg == 0) {
        int qa = q0 + wr0 + g, qb = qa + 8;
        if (qa < QQ) { pm[qa] = m0r; pl[qa] = l0; }
        if (qb < QQ) { pm[qb] = m1r; pl[qb] = l1; }
    }
}

// ---------------- split-K combine ----------------
__global__ void combine_kernel(float* __restrict__ attno) {
    int idx = blockIdx.x * 256 + threadIdx.x;
    if (idx >= ZZ * QQ * HD) return;
    int c = idx & (HD - 1);
    int q = (idx >> 5) % QQ;
    int z = idx / (HD * QQ);
    int b = z / NH, h = z % NH;

    float m = -1e30f;
    #pragma unroll
    for (int s = 0; s < NSPLIT; s++)
        m = fmaxf(m, g_pm[(s * ZZ + z) * QQ + q]);
    float o = 0.f, l = 0.f;
    #pragma unroll
    for (int s = 0; s < NSPLIT; s++) {
        float w = __expf(g_pm[(s * ZZ + z) * QQ + q] - m);
        l += g_pl[(s * ZZ + z) * QQ + q] * w;
        o += g_po[(((size_t)s * ZZ + z) * QQ + q) * HD + c] * w;
    }
    attno[((size_t)b * QQ + q) * CC + h * HD + c] = o / l;
}

// ---------------- host launcher ----------------
extern "C" void kernel_launch(void* const* d_in, const int* in_sizes, int n_in,
                              void* d_out, int out_size) {
    const float* f0   = (const float*)d_in[0];
    const float* f1   = (const float*)d_in[1];
    const float* refs = (const float*)d_in[2];
    const float* intr = (const float*)d_in[3];
    const float* extr = (const float*)d_in[4];
    const float* qry  = (const float*)d_in[5];
    const float* Wq   = (const float*)d_in[6];
    const float* bq   = (const float*)d_in[7];
    const float* Wk   = (const float*)d_in[8];
    const float* bk   = (const float*)d_in[9];
    const float* Wv   = (const float*)d_in[10];
    const float* bv   = (const float*)d_in[11];
    const float* Wo   = (const float*)d_in[12];
    const float* bo   = (const float*)d_in[13];
    float* out = (float*)d_out;

    __half *qp, *kp, *vp;
    float *sampled, *attno;
    cudaGetSymbolAddress((void**)&sampled, g_sampled);
    cudaGetSymbolAddress((void**)&qp, g_qp);
    cudaGetSymbolAddress((void**)&kp, g_kp);
    cudaGetSymbolAddress((void**)&vp, g_vp);
    cudaGetSymbolAddress((void**)&attno, g_attno);

    cudaFuncSetAttribute(gemm_qkv, cudaFuncAttributeMaxDynamicSharedMemorySize, GEMM_SMEM);
    cudaFuncSetAttribute(gemm_proj, cudaFuncAttributeMaxDynamicSharedMemorySize, GEMM_SMEM);
    cudaFuncSetAttribute(flash_kernel, cudaFuncAttributeMaxDynamicSharedMemorySize, FLASH_SMEM);

    const int NTILES = (PT0 * 4 + PT1 * 4) * BB * VV;
    transpose_kernel<<<NTILES, 256>>>(f0, f1);
    sample_kernel<<<(BB * QQ) / 4, dim3(64, 4)>>>(refs, intr, extr);

    const int M = BB * QQ;  // 1800
    gemm_qkv<<<dim3(CC / 64, (M + 63) / 64, 3), 256, GEMM_SMEM>>>(
        qry, sampled, Wq, Wk, Wv, bq, bk, bv, qp, kp, vp);

    flash_kernel<<<dim3((QQ + 63) / 64, ZZ, NSPLIT), 128, FLASH_SMEM>>>(qp, kp, vp);
    combine_kernel<<<(ZZ * QQ * HD + 255) / 256, 256>>>(attno);

    gemm_proj<<<dim3(CC / 64, (M + 63) / 64), 256, GEMM_SMEM>>>(attno, Wo, out, bo);
}